// round 15
// baseline (speedup 1.0000x reference)
#include <cuda_runtime.h>

#define D_DIM   768
#define F4_ROW  (D_DIM / 4)        // 192 float4 per row
#define F4_LANE 6                  // float4 per lane (192/32)
#define WARPS   8
#define NTHR    (WARPS * 32)       // 256 threads
#define RPW     8                  // rows per warp (4 pairs)
#define PAIRS   (RPW / 2)
#define LN_EPS  1e-6f

__global__ __launch_bounds__(NTHR, 2)   // cap 128 regs -> 2 CTA/SM
void hier_attn_ln_kernel(const int*   __restrict__ ids,
                         const float* __restrict__ pooler,
                         const float* __restrict__ emb,     // (V,2)
                         const float* __restrict__ Wd,      // (2,D)
                         const float* __restrict__ bd,      // (D)
                         const float* __restrict__ gamma,   // (D)
                         const float* __restrict__ beta,    // (D)
                         float*       __restrict__ out,
                         int L)
{
    __shared__ float4 sX [F4_ROW];   // x (per batch)
    __shared__ float4 sG [F4_ROW];   // gamma
    __shared__ float4 sBE[F4_ROW];   // beta
    __shared__ float  sred[WARPS][2];
    __shared__ float  sSx, sXX;

    const int b    = blockIdx.y;
    const int warp = threadIdx.x >> 5;
    const int lane = threadIdx.x & 31;
    const int t    = threadIdx.x;

    // ---- block prologue: x/gamma/beta into smem; block-reduce Sx, xx ----
    const int   id = __ldg(ids + b);
    const float e0 = __ldg(emb + 2 * id);
    const float e1 = __ldg(emb + 2 * id + 1);

    float sxp = 0.f, xxp = 0.f;
    if (t < F4_ROW) {
        float4 w0 = reinterpret_cast<const float4*>(Wd)[t];
        float4 w1 = reinterpret_cast<const float4*>(Wd + D_DIM)[t];
        float4 bb = reinterpret_cast<const float4*>(bd)[t];
        float4 v;
        v.x = fmaf(e0, w0.x, fmaf(e1, w1.x, bb.x));
        v.y = fmaf(e0, w0.y, fmaf(e1, w1.y, bb.y));
        v.z = fmaf(e0, w0.z, fmaf(e1, w1.z, bb.z));
        v.w = fmaf(e0, w0.w, fmaf(e1, w1.w, bb.w));
        sX [t] = v;
        sG [t] = reinterpret_cast<const float4*>(gamma)[t];
        sBE[t] = reinterpret_cast<const float4*>(beta)[t];
        sxp = v.x + v.y + v.z + v.w;
        xxp = fmaf(v.x, v.x, fmaf(v.y, v.y, fmaf(v.z, v.z, v.w * v.w)));
    }
    #pragma unroll
    for (int off = 16; off > 0; off >>= 1) {
        sxp += __shfl_xor_sync(0xffffffffu, sxp, off);
        xxp += __shfl_xor_sync(0xffffffffu, xxp, off);
    }
    if (lane == 0) { sred[warp][0] = sxp; sred[warp][1] = xxp; }
    __syncthreads();
    if (t == 0) {
        float a = 0.f, c = 0.f;
        #pragma unroll
        for (int w = 0; w < WARPS; ++w) { a += sred[w][0]; c += sred[w][1]; }
        sSx = a; sXX = c;
    }
    __syncthreads();
    const float Sx = sSx, xx = sXX;

    const int l0 = (blockIdx.x * WARPS + warp) * RPW;
    if (l0 >= L) return;
    const int nrows = min(RPW, L - l0);

    const float invD = 1.0f / (float)D_DIM;
    const float* rowPtr = pooler + ((size_t)b * L + l0) * D_DIM;
    float*       outPtr = out    + ((size_t)b * L + l0) * D_DIM;

    // ---- pair-wise double-buffered pipeline: 2 rows per chain traversal ----
    float4 pA[2][F4_LANE], pB[2][F4_LANE];

    {   // prologue: load pair 0 (rows 0,1) — 12 LDG.128 in flight
        const float4* r0 = reinterpret_cast<const float4*>(rowPtr);
        const int rb = (1 < nrows) ? 1 : 0;
        const float4* r1 = reinterpret_cast<const float4*>(rowPtr + (size_t)rb * D_DIM);
        #pragma unroll
        for (int j = 0; j < F4_LANE; ++j) {
            pA[0][j] = __ldcs(r0 + lane + 32 * j);
            pB[0][j] = __ldcs(r1 + lane + 32 * j);
        }
    }

    #pragma unroll
    for (int k = 0; k < PAIRS; ++k) {
        const int rA = 2 * k;
        if (rA >= nrows) break;
        const int rB = (rA + 1 < nrows) ? rA + 1 : rA;
        const int cur = k & 1, nxt = cur ^ 1;

        // prefetch next pair BEFORE the dependent chain (12 LDG in flight)
        if (2 * (k + 1) < nrows) {
            const int nA = 2 * (k + 1);
            const int nB = (nA + 1 < nrows) ? nA + 1 : nA;
            const float4* ra = reinterpret_cast<const float4*>(rowPtr + (size_t)nA * D_DIM);
            const float4* rb = reinterpret_cast<const float4*>(rowPtr + (size_t)nB * D_DIM);
            #pragma unroll
            for (int j = 0; j < F4_LANE; ++j) {
                pA[nxt][j] = __ldcs(ra + lane + 32 * j);
                pB[nxt][j] = __ldcs(rb + lane + 32 * j);
            }
        }

        // partials for BOTH rows (x read once from smem per j, serves both)
        float ppA = 0.f, pxA = 0.f, SpA = 0.f;
        float ppB = 0.f, pxB = 0.f, SpB = 0.f;
        #pragma unroll
        for (int j = 0; j < F4_LANE; ++j) {
            const float4 xj = sX[lane + 32 * j];
            const float4 a = pA[cur][j];
            const float4 bv = pB[cur][j];
            ppA = fmaf(a.x, a.x,  fmaf(a.y, a.y,  fmaf(a.z, a.z,  fmaf(a.w, a.w,  ppA))));
            pxA = fmaf(a.x, xj.x, fmaf(a.y, xj.y, fmaf(a.z, xj.z, fmaf(a.w, xj.w, pxA))));
            SpA += a.x + a.y + a.z + a.w;
            ppB = fmaf(bv.x, bv.x,  fmaf(bv.y, bv.y,  fmaf(bv.z, bv.z,  fmaf(bv.w, bv.w,  ppB))));
            pxB = fmaf(bv.x, xj.x,  fmaf(bv.y, xj.y,  fmaf(bv.z, xj.z,  fmaf(bv.w, xj.w,  pxB))));
            SpB += bv.x + bv.y + bv.z + bv.w;
        }

        // 6 independent butterflies pipeline through 5 SHFL levels
        #pragma unroll
        for (int off = 16; off > 0; off >>= 1) {
            ppA += __shfl_xor_sync(0xffffffffu, ppA, off);
            ppB += __shfl_xor_sync(0xffffffffu, ppB, off);
            pxA += __shfl_xor_sync(0xffffffffu, pxA, off);
            pxB += __shfl_xor_sync(0xffffffffu, pxB, off);
            SpA += __shfl_xor_sync(0xffffffffu, SpA, off);
            SpB += __shfl_xor_sync(0xffffffffu, SpB, off);
        }

        // coefficients for A and B (independent scalar chains)
        float wpA = __fdividef(1.f, 1.f + __expf(pxA - ppA))
                  + __fdividef(1.f, 1.f + __expf(xx - pxA));
        float wxA = 2.0f - wpA;
        float wpB = __fdividef(1.f, 1.f + __expf(pxB - ppB))
                  + __fdividef(1.f, 1.f + __expf(xx - pxB));
        float wxB = 2.0f - wpB;

        float meanA = (wpA * SpA + wxA * Sx) * invD;
        float invA  = rsqrtf((wpA*wpA*ppA + 2.f*wpA*wxA*pxA + wxA*wxA*xx) * invD
                             - meanA * meanA + LN_EPS);
        float cwpA = wpA * invA, cwxA = wxA * invA, ncmA = -meanA * invA;

        float meanB = (wpB * SpB + wxB * Sx) * invD;
        float invB  = rsqrtf((wpB*wpB*ppB + 2.f*wpB*wxB*pxB + wxB*wxB*xx) * invD
                             - meanB * meanB + LN_EPS);
        float cwpB = wpB * invB, cwxB = wxB * invB, ncmB = -meanB * invB;

        // epilogue for both rows (g/be/x read once per j, serve both)
        float4* orA = reinterpret_cast<float4*>(outPtr + (size_t)rA * D_DIM);
        float4* orB = reinterpret_cast<float4*>(outPtr + (size_t)rB * D_DIM);
        const bool doB = (rA + 1 < nrows);
        #pragma unroll
        for (int j = 0; j < F4_LANE; ++j) {
            const int c = lane + 32 * j;
            const float4 xj = sX[c];
            const float4 g  = sG[c];
            const float4 be = sBE[c];
            const float4 a  = pA[cur][j];
            float4 o;
            o.x = fmaf(fmaf(cwpA, a.x, fmaf(cwxA, xj.x, ncmA)), g.x, be.x);
            o.y = fmaf(fmaf(cwpA, a.y, fmaf(cwxA, xj.y, ncmA)), g.y, be.y);
            o.z = fmaf(fmaf(cwpA, a.z, fmaf(cwxA, xj.z, ncmA)), g.z, be.z);
            o.w = fmaf(fmaf(cwpA, a.w, fmaf(cwxA, xj.w, ncmA)), g.w, be.w);
            orA[c] = o;
            if (doB) {
                const float4 bv = pB[cur][j];
                float4 ob;
                ob.x = fmaf(fmaf(cwpB, bv.x, fmaf(cwxB, xj.x, ncmB)), g.x, be.x);
                ob.y = fmaf(fmaf(cwpB, bv.y, fmaf(cwxB, xj.y, ncmB)), g.y, be.y);
                ob.z = fmaf(fmaf(cwpB, bv.z, fmaf(cwxB, xj.z, ncmB)), g.z, be.z);
                ob.w = fmaf(fmaf(cwpB, bv.w, fmaf(cwxB, xj.w, ncmB)), g.w, be.w);
                orB[c] = ob;
            }
        }
    }
}

extern "C" void kernel_launch(void* const* d_in, const int* in_sizes, int n_in,
                              void* d_out, int out_size)
{
    const int*   ids    = (const int*)  d_in[0];
    const float* pooler = (const float*)d_in[1];
    const float* emb    = (const float*)d_in[2];
    const float* Wd     = (const float*)d_in[3];
    const float* bd     = (const float*)d_in[4];
    const float* gamma  = (const float*)d_in[5];
    const float* beta   = (const float*)d_in[6];
    float* out = (float*)d_out;

    const int B = in_sizes[0];                      // ids is (B,1)
    const int L = in_sizes[1] / (B * D_DIM);        // pooler is (B,L,D)

    dim3 grid((L + WARPS * RPW - 1) / (WARPS * RPW), B);
    hier_attn_ln_kernel<<<grid, NTHR>>>(ids, pooler, emb, Wd, bd, gamma, beta, out, L);
}

// round 16
// speedup vs baseline: 1.5932x; 1.5932x over previous
#include <cuda_runtime.h>

#define D_DIM   768
#define F4_ROW  (D_DIM / 4)        // 192 float4 per row
#define F4_LANE 6                  // float4 per lane (192/32)
#define WARPS   8
#define NTHR    (WARPS * 32)       // 256 threads
#define RPW     8                  // rows per warp
#define LN_EPS  1e-6f

__global__ __launch_bounds__(NTHR, 2)   // cap 128 regs -> 2 CTA/SM
void hier_attn_ln_kernel(const int*   __restrict__ ids,
                         const float* __restrict__ pooler,
                         const float* __restrict__ emb,     // (V,2)
                         const float* __restrict__ Wd,      // (2,D)
                         const float* __restrict__ bd,      // (D)
                         const float* __restrict__ gamma,   // (D)
                         const float* __restrict__ beta,    // (D)
                         float*       __restrict__ out,
                         int L)
{
    __shared__ float4 sX [F4_ROW];   // x (per batch)
    __shared__ float4 sG [F4_ROW];   // gamma
    __shared__ float4 sBE[F4_ROW];   // beta
    __shared__ float  sred[WARPS][2];
    __shared__ float  sSx, sXX;

    const int b    = blockIdx.y;
    const int warp = threadIdx.x >> 5;
    const int lane = threadIdx.x & 31;
    const int t    = threadIdx.x;

    // ---- block prologue: x/gamma/beta into smem; block-reduce Sx, xx ----
    const int   id = __ldg(ids + b);
    const float e0 = __ldg(emb + 2 * id);
    const float e1 = __ldg(emb + 2 * id + 1);

    float sxp = 0.f, xxp = 0.f;
    if (t < F4_ROW) {
        float4 w0 = reinterpret_cast<const float4*>(Wd)[t];
        float4 w1 = reinterpret_cast<const float4*>(Wd + D_DIM)[t];
        float4 bb = reinterpret_cast<const float4*>(bd)[t];
        float4 v;
        v.x = fmaf(e0, w0.x, fmaf(e1, w1.x, bb.x));
        v.y = fmaf(e0, w0.y, fmaf(e1, w1.y, bb.y));
        v.z = fmaf(e0, w0.z, fmaf(e1, w1.z, bb.z));
        v.w = fmaf(e0, w0.w, fmaf(e1, w1.w, bb.w));
        sX [t] = v;
        sG [t] = reinterpret_cast<const float4*>(gamma)[t];
        sBE[t] = reinterpret_cast<const float4*>(beta)[t];
        sxp = v.x + v.y + v.z + v.w;
        xxp = fmaf(v.x, v.x, fmaf(v.y, v.y, fmaf(v.z, v.z, v.w * v.w)));
    }
    #pragma unroll
    for (int off = 16; off > 0; off >>= 1) {
        sxp += __shfl_xor_sync(0xffffffffu, sxp, off);
        xxp += __shfl_xor_sync(0xffffffffu, xxp, off);
    }
    if (lane == 0) { sred[warp][0] = sxp; sred[warp][1] = xxp; }
    __syncthreads();
    if (t == 0) {
        float a = 0.f, c = 0.f;
        #pragma unroll
        for (int w = 0; w < WARPS; ++w) { a += sred[w][0]; c += sred[w][1]; }
        sSx = a; sXX = c;
    }
    __syncthreads();
    const float Sx = sSx, xx = sXX;

    const int l0 = (blockIdx.x * WARPS + warp) * RPW;
    if (l0 >= L) return;
    const int nrows = min(RPW, L - l0);

    const float invD = 1.0f / (float)D_DIM;
    const float* rowPtr = pooler + ((size_t)b * L + l0) * D_DIM;
    float*       outPtr = out    + ((size_t)b * L + l0) * D_DIM;

    // ---- 3-buffer pipeline, prefetch distance 2, epilogue in-iteration ----
    // Buffer (r+2)%3 is fully consumed at end of iteration r-1 (epilogue is
    // in-iteration), so prefetching into it at the top of iteration r is safe.
    float4 pb[3][F4_LANE];

    #pragma unroll
    for (int j = 0; j < F4_LANE; ++j)
        pb[0][j] = __ldcs(reinterpret_cast<const float4*>(rowPtr) + lane + 32 * j);
    if (nrows > 1) {
        const float4* r1 = reinterpret_cast<const float4*>(rowPtr + D_DIM);
        #pragma unroll
        for (int j = 0; j < F4_LANE; ++j)
            pb[1][j] = __ldcs(r1 + lane + 32 * j);
    }

    #pragma unroll
    for (int r = 0; r < RPW; ++r) {
        if (r >= nrows) break;

        // prefetch row r+2 (12 loads now pending: r+1's and r+2's)
        if (r + 2 < nrows) {
            const float4* nr = reinterpret_cast<const float4*>(rowPtr + (size_t)(r + 2) * D_DIM);
            #pragma unroll
            for (int j = 0; j < F4_LANE; ++j)
                pb[(r + 2) % 3][j] = __ldcs(nr + lane + 32 * j);
        }

        // partials of row r (x from smem; one LDS.128 per j)
        float4 (&p)[F4_LANE] = pb[r % 3];
        float pp = 0.f, px = 0.f, Sp = 0.f;
        #pragma unroll
        for (int j = 0; j < F4_LANE; ++j) {
            const float4 xj = sX[lane + 32 * j];
            pp = fmaf(p[j].x, p[j].x, fmaf(p[j].y, p[j].y, fmaf(p[j].z, p[j].z, fmaf(p[j].w, p[j].w, pp))));
            px = fmaf(p[j].x, xj.x,   fmaf(p[j].y, xj.y,   fmaf(p[j].z, xj.z,   fmaf(p[j].w, xj.w,   px))));
            Sp += p[j].x + p[j].y + p[j].z + p[j].w;
        }
        #pragma unroll
        for (int off = 16; off > 0; off >>= 1) {
            pp += __shfl_xor_sync(0xffffffffu, pp, off);
            px += __shfl_xor_sync(0xffffffffu, px, off);
            Sp += __shfl_xor_sync(0xffffffffu, Sp, off);
        }

        // softmax weights via sigmoids: wp = sig(pp-px) + sig(px-xx); wx = 2 - wp
        float wp = __fdividef(1.f, 1.f + __expf(px - pp))
                 + __fdividef(1.f, 1.f + __expf(xx - px));
        float wx = 2.0f - wp;

        // analytic layernorm stats of summed = wp*p + wx*x
        float mean = (wp * Sp + wx * Sx) * invD;
        float ss2  = wp*wp*pp + 2.0f*wp*wx*px + wx*wx*xx;
        float inv  = rsqrtf(ss2 * invD - mean * mean + LN_EPS);
        float cwp  = wp * inv;
        float cwx  = wx * inv;
        float ncm  = -mean * inv;

        // epilogue (in-iteration): o = g*(cwp*p + cwx*x + ncm) + beta
        float4* orow = reinterpret_cast<float4*>(outPtr + (size_t)r * D_DIM);
        #pragma unroll
        for (int j = 0; j < F4_LANE; ++j) {
            const int c = lane + 32 * j;
            const float4 xj = sX[c];
            const float4 g  = sG[c];
            const float4 be = sBE[c];
            float4 o;
            o.x = fmaf(fmaf(cwp, p[j].x, fmaf(cwx, xj.x, ncm)), g.x, be.x);
            o.y = fmaf(fmaf(cwp, p[j].y, fmaf(cwx, xj.y, ncm)), g.y, be.y);
            o.z = fmaf(fmaf(cwp, p[j].z, fmaf(cwx, xj.z, ncm)), g.z, be.z);
            o.w = fmaf(fmaf(cwp, p[j].w, fmaf(cwx, xj.w, ncm)), g.w, be.w);
            __stcs(orow + c, o);
        }
    }
}

extern "C" void kernel_launch(void* const* d_in, const int* in_sizes, int n_in,
                              void* d_out, int out_size)
{
    const int*   ids    = (const int*)  d_in[0];
    const float* pooler = (const float*)d_in[1];
    const float* emb    = (const float*)d_in[2];
    const float* Wd     = (const float*)d_in[3];
    const float* bd     = (const float*)d_in[4];
    const float* gamma  = (const float*)d_in[5];
    const float* beta   = (const float*)d_in[6];
    float* out = (float*)d_out;

    const int B = in_sizes[0];                      // ids is (B,1)
    const int L = in_sizes[1] / (B * D_DIM);        // pooler is (B,L,D)

    dim3 grid((L + WARPS * RPW - 1) / (WARPS * RPW), B);
    hier_attn_ln_kernel<<<grid, NTHR>>>(ids, pooler, emb, Wd, bd, gamma, beta, out, L);
}